// round 7
// baseline (speedup 1.0000x reference)
#include <cuda_runtime.h>
#include <math.h>

// ---------------------------------------------------------------------------
// FCOS3D target assignment — round 7: warp-autonomous filter (no block
// barrier) + GT0 payload prefetch (removes the dependent second global RT
// for the ~97% background points).
// Each warp: 2 GTs/lane in regs (1 RT, concurrent with GT0 payload prefetch),
// analytic per-warp point bbox, ballot + ordered compaction into a per-warp
// smem segment, __syncwarp, tiny smem scan, stores.
// ---------------------------------------------------------------------------

#define NLVL 5
#define NPTS 30929
#define INF_ 1.0e8f

__device__ __constant__ int   c_off[NLVL + 1] = {0, 23200, 29000, 30450, 30825, 30929};
__device__ __constant__ int   c_w[NLVL]       = {200, 100, 50, 25, 13};
__device__ __constant__ float c_s[NLVL]       = {8.f, 16.f, 32.f, 64.f, 128.f};
__device__ __constant__ float c_inv_s[NLVL]   = {0.125f, 0.0625f, 0.03125f, 0.015625f, 0.0078125f};
__device__ __constant__ float c_cent_k[NLVL]  = {
    -2.5f / (1.414f * 8.f   * 1.5f),
    -2.5f / (1.414f * 16.f  * 1.5f),
    -2.5f / (1.414f * 32.f  * 1.5f),
    -2.5f / (1.414f * 64.f  * 1.5f),
    -2.5f / (1.414f * 128.f * 1.5f)};
__device__ __constant__ float c_r0[NLVL]      = {-1.f, 48.f, 96.f, 192.f, 384.f};
__device__ __constant__ float c_r1[NLVL]      = {48.f, 96.f, 192.f, 384.f, 1.0e8f};

#define NWARP 4   // 128-thread blocks

__global__ void __launch_bounds__(128)
fcos3d_target_kernel(
    const float* __restrict__ gt_bboxes,    // (B, M, 4)
    const float* __restrict__ g3d,          // (B, M, 9)
    const int*   __restrict__ gl3d,         // (B, M)
    const float* __restrict__ centers2d,    // (B, M, 2)
    const float* __restrict__ depths,       // (B, M)
    const int*   __restrict__ attrs,        // (B, M)
    float*       __restrict__ out,
    int M, int B)
{
    const int b    = blockIdx.y;
    const int tid  = threadIdx.x;
    const int lane = tid & 31;
    const int wid  = tid >> 5;

    // Per-warp candidate segments (max M=64 each).
    __shared__ float4 s_cbb[NWARP][64];
    __shared__ float2 s_cc[NWARP][64];
    __shared__ int    s_cidx[NWARP][64];

    // ---- point coords (clamped for warp convergence) ----
    const int n_raw = blockIdx.x * blockDim.x + tid;
    const bool valid = (n_raw < NPTS);
    const int n = valid ? n_raw : (NPTS - 1);

    int lvl = 0;
#pragma unroll
    for (int i = 1; i < NLVL; i++)
        if (n >= c_off[i]) lvl = i;

    const int   p   = n - c_off[lvl];
    const int   w   = c_w[lvl];
    const float s   = c_s[lvl];
    const float x   = (float)(p % w) * s + 0.5f * s;
    const float y   = (float)(p / w) * s + 0.5f * s;
    const float r0  = c_r0[lvl];
    const float r1  = c_r1[lvl];
    const float rad = s * 1.5f;

    // ---- issue all independent loads up front (one latency window) ----
    const float2* cptr = reinterpret_cast<const float2*>(centers2d) + (size_t)b * M;
    const float4* bptr = reinterpret_cast<const float4*>(gt_bboxes) + (size_t)b * M;

    float2 myc[2];
    float4 mybb[2];
#pragma unroll
    for (int r = 0; r < 2; r++) {
        const int m = r * 32 + lane;
        if (m < M) { myc[r] = cptr[m]; mybb[r] = bptr[m]; }
        else       { myc[r] = make_float2(-2e30f, -2e30f); }
    }

    // GT0 payload prefetch (broadcast loads; covers the background case).
    const int gi0 = b * M;
    const float* g0p = g3d + (size_t)gi0 * 9;
    float  p_g0 = g0p[0], p_g2 = g0p[2], p_g3 = g0p[3], p_g4 = g0p[4];
    float  p_g5 = g0p[5], p_g6 = g0p[6], p_g7 = g0p[7], p_g8 = g0p[8];
    float  p_d  = depths[gi0];
    float  p_l  = (float)gl3d[gi0];
    float  p_a  = (float)attrs[gi0];
    float2 c0   = cptr[0];

    // ---- analytic per-warp point bbox (all lanes compute identically) ----
    const int wn0   = blockIdx.x * blockDim.x + wid * 32;
    const int wlast = min(wn0 + 31, NPTS - 1);
    const int wfirst = min(wn0, NPTS - 1);
    float bxmin = 1e30f, bxmax = -1e30f;
    float bymin = 1e30f, bymax = -1e30f, rmx = 0.f;
#pragma unroll
    for (int l = 0; l < NLVL; l++) {
        const int a = max(wfirst, c_off[l]);
        const int e = min(wlast, c_off[l + 1] - 1);
        if (a > e) continue;
        const int   pw = c_w[l];
        const float ls = c_s[l];
        const int p0 = a - c_off[l], p1 = e - c_off[l];
        const int row0 = p0 / pw, row1 = p1 / pw;
        const int xlo = (row1 > row0) ? 0 : (p0 % pw);
        const int xhi = (row1 > row0) ? (pw - 1) : (p1 % pw);
        bxmin = fminf(bxmin, (float)xlo * ls + 0.5f * ls);
        bxmax = fmaxf(bxmax, (float)xhi * ls + 0.5f * ls);
        bymin = fminf(bymin, (float)row0 * ls + 0.5f * ls);
        bymax = fmaxf(bymax, (float)row1 * ls + 0.5f * ls);
        rmx   = fmaxf(rmx, 1.5f * ls);
    }
    bxmin -= rmx; bxmax += rmx; bymin -= rmx; bymax += rmx;

    // ---- ballot filter + ordered compaction into this warp's segment ----
    int cnt = 0;
#pragma unroll
    for (int r = 0; r < 2; r++) {
        const int m = r * 32 + lane;
        const bool ok = (m < M) &
                        (myc[r].x >= bxmin) & (myc[r].x <= bxmax) &
                        (myc[r].y >= bymin) & (myc[r].y <= bymax);
        const unsigned mask = __ballot_sync(0xffffffffu, ok);
        if (ok) {
            const int pos = cnt + __popc(mask & ((1u << lane) - 1u));
            s_cbb[wid][pos]  = mybb[r];
            s_cc[wid][pos]   = myc[r];
            s_cidx[wid][pos] = m;
        }
        cnt += __popc(mask);
    }
    __syncwarp();

    // ---- argmin over candidates (squared distance; first-min tie-break) ----
    float best = INF_;
    int   bk   = -1;
    for (int k = 0; k < cnt; k++) {
        const float4 bb = s_cbb[wid][k];
        const float2 c  = s_cc[wid][k];
        const float dx = x - c.x;
        const float dy = y - c.y;
        const float mrd = fmaxf(fmaxf(x - bb.x, y - bb.y),
                                fmaxf(bb.z - x, bb.w - y));
        const bool ok = (mrd >= r0) & (mrd <= r1) &
                        (fmaxf(fabsf(dx), fabsf(dy)) < rad);
        const float d2 = ok ? fmaf(dx, dx, dy * dy) : INF_;
        if (d2 < best) { best = d2; bk = k; }
    }

    if (!valid) return;

    // bk >= 0 <=> foreground (d2 < INF occurred). bg -> GT index 0.
    const bool bg = (bk < 0);
    float2 c = c0;
    if (!bg) {
        c = s_cc[wid][bk];
        const int bi = s_cidx[wid][bk];
        const int gi = b * M + bi;
        const float* g = g3d + (size_t)gi * 9;
        p_g0 = g[0]; p_g2 = g[2]; p_g3 = g[3]; p_g4 = g[4];
        p_g5 = g[5]; p_g6 = g[6]; p_g7 = g[7]; p_g8 = g[8];
        p_d  = depths[gi];
        p_l  = (float)gl3d[gi];
        p_a  = (float)attrs[gi];
    }

    const float dx = x - c.x;
    const float dy = y - c.y;
    const float yaw  = -atan2f(p_g0, p_g2) + p_g6;
    const float cent = expf(c_cent_k[lvl] * sqrtf(fmaf(dx, dx, dy * dy)));

    const int BN   = B * NPTS;
    const int npl  = c_off[lvl + 1] - c_off[lvl];
    const int base = c_off[lvl] * B + b * npl + p;
    const float inv_s = c_inv_s[lvl];

    out[base]           = bg ? 10.f : p_l;   // labels_3d
    out[10 * BN + base] = cent;              // centerness
    out[11 * BN + base] = bg ? 9.f : p_a;    // attr

    float* bo = out + BN + (size_t)base * 9; // bbox_targets_3d
    bo[0] = dx * inv_s;
    bo[1] = dy * inv_s;
    bo[2] = p_d;
    bo[3] = p_g3;
    bo[4] = p_g4;
    bo[5] = p_g5;
    bo[6] = yaw;
    bo[7] = p_g7;
    bo[8] = p_g8;
}

extern "C" void kernel_launch(void* const* d_in, const int* in_sizes, int n_in,
                              void* d_out, int out_size)
{
    const float* gt_bboxes = (const float*)d_in[0];
    const float* g3d       = (const float*)d_in[2];
    const int*   gl3d      = (const int*)  d_in[3];
    const float* centers2d = (const float*)d_in[4];
    const float* depths    = (const float*)d_in[5];
    const int*   attrs     = (const int*)  d_in[6];
    float* out = (float*)d_out;

    const int B = out_size / (12 * NPTS);
    const int M = in_sizes[1] / B;

    const int threads = 128;
    dim3 grid((NPTS + threads - 1) / threads, B);
    fcos3d_target_kernel<<<grid, threads>>>(
        gt_bboxes, g3d, gl3d, centers2d, depths, attrs, out, M, B);
}